// round 9
// baseline (speedup 1.0000x reference)
#include <cuda_runtime.h>
#include <cstdint>

// Row-wise top-k(=6) thresholded renormalization.
//   delta = (6th largest of row) + 1e-7
//   w     = max(v - delta, 0) ;  out = w / (sum(w) + 1e-7)
//
// R9: one warp per row, grid=rows/8, unconstrained registers (load batching
// is sacred — R7 lesson). vs R8:
//  - stage B drops ballot/ffs: all tied lanes zero together => t = 6th
//    largest DISTINCT thread-max, still provably <= true 6th largest.
//  - compaction uses private per-lane slots (stride 33, conflict-free) +
//    counts; no serialized shared atomics.
//  - stage D (lane-0 insertion top-6, exact multiset) walks only the
//    ballot-mask lanes.
//  - clamp is in place (reg reuse) with NO launch-bounds cap.

#define COLS   1024
#define TOPK   6
#define EPSV   1e-7f
#define WPB    8            // warps (=rows) per block
#define CSTRIDE 33          // padded slots per lane (>=32, kills bank conflicts)

__device__ __forceinline__ unsigned redux_max_u32(unsigned v) {
    unsigned r;
    asm volatile("redux.sync.max.u32 %0, %1, %2;"
                 : "=r"(r) : "r"(v), "r"(0xffffffffu));
    return r;
}
// monotone bijection: float ordering -> u32 ordering (exact, invertible)
__device__ __forceinline__ unsigned fkey(float f) {
    unsigned b = __float_as_uint(f);
    return b ^ ((unsigned)((int)b >> 31) | 0x80000000u);
}
__device__ __forceinline__ float funkey(unsigned k) {
    unsigned b = (k & 0x80000000u) ? (k ^ 0x80000000u) : ~k;
    return __uint_as_float(b);
}
__device__ __forceinline__ float4 fmax4(float4 a, float4 b) {
    return make_float4(fmaxf(a.x,b.x), fmaxf(a.y,b.y),
                       fmaxf(a.z,b.z), fmaxf(a.w,b.w));
}

__global__ __launch_bounds__(32 * WPB)
void topk_renorm_kernel(const float* __restrict__ in,
                        float* __restrict__ out, int rows) {
    const int lane = threadIdx.x & 31;
    const int warp = threadIdx.x >> 5;
    const int row  = blockIdx.x * WPB + warp;
    if (row >= rows) return;

    __shared__ unsigned sh_cand[WPB][32 * CSTRIDE];  // private lane regions
    __shared__ int      sh_cnt[WPB][32];

    // ---- load: 32 elems/thread as 8 float4 (MLP=8, front-batched) ----
    const float4* rp = reinterpret_cast<const float4*>(in + (size_t)row * COLS);
    float4 v[8];
#pragma unroll
    for (int i = 0; i < 8; ++i) v[i] = __ldcs(rp + lane + 32 * i);

    // ---- per-thread max (31 FMNMX tree) ----
    float4 m01 = fmax4(v[0], v[1]), m23 = fmax4(v[2], v[3]);
    float4 m45 = fmax4(v[4], v[5]), m67 = fmax4(v[6], v[7]);
    float4 mm  = fmax4(fmax4(m01, m23), fmax4(m45, m67));
    float lmax = fmaxf(fmaxf(mm.x, mm.y), fmaxf(mm.z, mm.w));

    // ---- t = 6th largest DISTINCT thread-max (valid bound: t <= v6) ----
    unsigned a = fkey(lmax);
    unsigned kth = 0u;
#pragma unroll
    for (int r = 0; r < TOPK; ++r) {
        unsigned m = redux_max_u32(a);
        kth = m;
        if (a == m) a = 0u;          // ties removed together: distinct-kth
    }
    const float t = funkey(kth);     // identical on all lanes

    // ---- compact candidates (v >= t) into private lane slots ----
    const unsigned mask = __ballot_sync(0xffffffffu, lmax >= t);
    if (lmax >= t) {
        unsigned* buf = &sh_cand[warp][lane * CSTRIDE];
        int c = 0;
#pragma unroll
        for (int i = 0; i < 8; ++i) {
            if (v[i].x >= t) buf[c++] = fkey(v[i].x);
            if (v[i].y >= t) buf[c++] = fkey(v[i].y);
            if (v[i].z >= t) buf[c++] = fkey(v[i].z);
            if (v[i].w >= t) buf[c++] = fkey(v[i].w);
        }
        sh_cnt[warp][lane] = c;
    }
    __syncwarp();

    // ---- 6th largest of candidates: lane-0 insertion top-6 (exact) ----
    // At least 6 elements >= t exist, so s5 ends as the true 6th largest.
    float delta;
    if (lane == 0) {
        unsigned s0=0u,s1=0u,s2=0u,s3=0u,s4=0u,s5=0u;  // s0 >= ... >= s5
        unsigned mrem = mask;
        while (mrem) {
            const int l = __ffs((int)mrem) - 1; mrem &= mrem - 1u;
            const int cl = sh_cnt[warp][l];
            const unsigned* buf = &sh_cand[warp][l * CSTRIDE];
            for (int j = 0; j < cl; ++j) {
                unsigned x = buf[j];
                if (x > s5) {
                    if      (x > s0) { s5=s4;s4=s3;s3=s2;s2=s1;s1=s0;s0=x; }
                    else if (x > s1) { s5=s4;s4=s3;s3=s2;s2=s1;s1=x; }
                    else if (x > s2) { s5=s4;s4=s3;s3=s2;s2=x; }
                    else if (x > s3) { s5=s4;s4=s3;s3=x; }
                    else if (x > s4) { s5=s4;s4=x; }
                    else             { s5=x; }
                }
            }
        }
        delta = funkey(s5) + EPSV;
    }
    delta = __shfl_sync(0xffffffffu, delta, 0);   // broadcast

    // ---- epilogue: clamp IN PLACE, warp sum, normalize, store ----
    float4 acc = make_float4(0.f, 0.f, 0.f, 0.f);
#pragma unroll
    for (int i = 0; i < 8; ++i) {
        v[i].x = fmaxf(v[i].x - delta, 0.0f);
        v[i].y = fmaxf(v[i].y - delta, 0.0f);
        v[i].z = fmaxf(v[i].z - delta, 0.0f);
        v[i].w = fmaxf(v[i].w - delta, 0.0f);
        acc.x += v[i].x; acc.y += v[i].y; acc.z += v[i].z; acc.w += v[i].w;
    }
    float s = (acc.x + acc.y) + (acc.z + acc.w);
#pragma unroll
    for (int o = 16; o > 0; o >>= 1)
        s += __shfl_xor_sync(0xffffffffu, s, o);
    const float rinv = 1.0f / (s + EPSV);      // identical on all lanes

    float4* op = reinterpret_cast<float4*>(out + (size_t)row * COLS);
#pragma unroll
    for (int i = 0; i < 8; ++i) {
        float4 o4;
        o4.x = v[i].x * rinv; o4.y = v[i].y * rinv;
        o4.z = v[i].z * rinv; o4.w = v[i].w * rinv;
        __stcs(op + lane + 32 * i, o4);
    }
}

extern "C" void kernel_launch(void* const* d_in, const int* in_sizes, int n_in,
                              void* d_out, int out_size) {
    const float* in = (const float*)d_in[0];
    float* out = (float*)d_out;
    const int rows = in_sizes[0] / COLS;           // 65536 for reference shape
    const int grid = (rows + WPB - 1) / WPB;
    topk_renorm_kernel<<<grid, 32 * WPB>>>(in, out, rows);
}